// round 1
// baseline (speedup 1.0000x reference)
#include <cuda_runtime.h>
#include <math.h>

#define N_ATOMS 50000
#define N_EDGES 400000
#define N_MOLS  500
#define HID     128
#define NRBF    20
#define NLAYERS 4

// ---------------- device scratch (static, no allocations) ----------------
__device__ float g_rbf[N_EDGES * NRBF];
__device__ float g_dir[N_EDGES * 3];
__device__ float g_s[N_ATOMS * HID];
__device__ float g_v[N_ATOMS * HID * 3];
__device__ float g_ms[N_ATOMS * HID];
__device__ float g_mv[N_ATOMS * HID * 3];
__device__ float g_hmol[N_MOLS * HID];
__device__ float g_cnt[N_MOLS];

__device__ __forceinline__ float silu_f(float x) { return x / (1.0f + expf(-x)); }

// ---------------- geometry: dist, dirs, rbf ----------------
__global__ void geom_kernel(const float* __restrict__ pos, const int* __restrict__ ei) {
    int e = blockIdx.x * blockDim.x + threadIdx.x;
    if (e >= N_EDGES) return;
    int r = ei[e];
    int c = ei[N_EDGES + e];
    float dx = pos[c * 3 + 0] - pos[r * 3 + 0];
    float dy = pos[c * 3 + 1] - pos[r * 3 + 1];
    float dz = pos[c * 3 + 2] - pos[r * 3 + 2];
    float dist = sqrtf(dx * dx + dy * dy + dz * dz);
    float inv = 1.0f / (dist + 1e-8f);
    g_dir[e * 3 + 0] = dx * inv;
    g_dir[e * 3 + 1] = dy * inv;
    g_dir[e * 3 + 2] = dz * inv;
    const float step = 5.0f / (float)(NRBF - 1);
#pragma unroll
    for (int k = 0; k < NRBF; k++) {
        float d = dist - step * (float)k;
        g_rbf[e * NRBF + k] = expf(-d * d);
    }
}

// ---------------- init: s = emb[z], v = 0, ms = 0, mv = 0 ----------------
__global__ void init_kernel(const int* __restrict__ z, const float* __restrict__ emb) {
    int idx = blockIdx.x * blockDim.x + threadIdx.x;
    if (idx >= N_ATOMS * HID) return;
    int n = idx >> 7;
    int j = idx & 127;
    g_s[idx] = emb[z[n] * HID + j];
    g_ms[idx] = 0.0f;
    int vb = idx * 3;
    g_v[vb + 0] = 0.0f; g_v[vb + 1] = 0.0f; g_v[vb + 2] = 0.0f;
    g_mv[vb + 0] = 0.0f; g_mv[vb + 1] = 0.0f; g_mv[vb + 2] = 0.0f;
}

// ---------------- fused edge kernel (per layer) ----------------
// 64-edge tile, 512 threads.
// Stage1: hidden = silu(rbf @ W1 + b1)   (64 x 128) in smem
// Stage2: h = hidden @ W2 + b2           (64 x 384), 3 accumulators per (e,j)
// Stage3: messages + atomic scatter into g_ms / g_mv
#define ET 64
// smem float layout:
//  hid   : [0, 8448)           64 x 132
//  rbf_s : [8448, 9728)        64 x 20     (stage1 only)
//  w1_s  : [9728, 12288)       20 x 128    (stage1 only)
//  w2_s  : [8448, 20736)       32 x 384    (stage2, overlaps rbf/w1)
//  row/col/dir : [20736, 21056)
#define EDGE_SMEM_FLOATS 21056

extern "C" __global__ void __launch_bounds__(512, 1)
edge_kernel(int layer, const int* __restrict__ ei,
            const float* __restrict__ fW1, const float* __restrict__ fb1,
            const float* __restrict__ fW2, const float* __restrict__ fb2) {
    extern __shared__ float sm[];
    float* hid = sm;                    // [64][132]
    float* rbf_s = sm + 8448;           // [64][20]
    float* w1_s = sm + 9728;            // [20][128]
    float* w2_s = sm + 8448;            // [32][384]
    int* row_s = (int*)(sm + 20736);
    int* col_s = row_s + 64;
    float* dir_s = sm + 20736 + 128;    // [64][3]

    const int tid = threadIdx.x;
    const int e0 = blockIdx.x * ET;
    const float* W1 = fW1 + layer * NRBF * HID;
    const float* b1 = fb1 + layer * HID;
    const float* W2 = fW2 + layer * HID * 3 * HID;
    const float* b2 = fb2 + layer * 3 * HID;

    for (int idx = tid; idx < ET * NRBF; idx += 512) rbf_s[idx] = g_rbf[e0 * NRBF + idx];
    for (int idx = tid; idx < NRBF * HID; idx += 512) w1_s[idx] = W1[idx];
    for (int idx = tid; idx < ET; idx += 512) {
        row_s[idx] = ei[e0 + idx];
        col_s[idx] = ei[N_EDGES + e0 + idx];
    }
    for (int idx = tid; idx < ET * 3; idx += 512) dir_s[idx] = g_dir[e0 * 3 + idx];
    __syncthreads();

    const int jg = tid & 31;
    const int eg = tid >> 5;
    const int j0 = jg * 4;
    const int el0 = eg * 4;

    // ---- stage 1 ----
    float hacc[4][4];
#pragma unroll
    for (int a = 0; a < 4; a++)
#pragma unroll
        for (int b = 0; b < 4; b++) hacc[a][b] = b1[j0 + b];
#pragma unroll
    for (int k = 0; k < NRBF; k++) {
        float r[4];
#pragma unroll
        for (int a = 0; a < 4; a++) r[a] = rbf_s[(el0 + a) * NRBF + k];
        float4 w = *(const float4*)&w1_s[k * HID + j0];
        float wv[4] = {w.x, w.y, w.z, w.w};
#pragma unroll
        for (int a = 0; a < 4; a++)
#pragma unroll
            for (int b = 0; b < 4; b++) hacc[a][b] += r[a] * wv[b];
    }
#pragma unroll
    for (int a = 0; a < 4; a++)
#pragma unroll
        for (int b = 0; b < 4; b++) hid[(el0 + a) * 132 + j0 + b] = silu_f(hacc[a][b]);
    __syncthreads();

    // ---- stage 2 ----
    float a_ss[4][4], a_vv[4][4], a_sv[4][4];
#pragma unroll
    for (int a = 0; a < 4; a++)
#pragma unroll
        for (int b = 0; b < 4; b++) { a_ss[a][b] = 0.f; a_vv[a][b] = 0.f; a_sv[a][b] = 0.f; }

    for (int kc = 0; kc < HID; kc += 32) {
        __syncthreads();
        for (int idx = tid; idx < 32 * 384; idx += 512) w2_s[idx] = W2[kc * 384 + idx];
        __syncthreads();
#pragma unroll 8
        for (int kk = 0; kk < 32; kk++) {
            float h[4];
#pragma unroll
            for (int a = 0; a < 4; a++) h[a] = hid[(el0 + a) * 132 + kc + kk];
            float4 wss = *(const float4*)&w2_s[kk * 384 + j0];
            float4 wvv = *(const float4*)&w2_s[kk * 384 + 128 + j0];
            float4 wsv = *(const float4*)&w2_s[kk * 384 + 256 + j0];
            float ss[4] = {wss.x, wss.y, wss.z, wss.w};
            float vv[4] = {wvv.x, wvv.y, wvv.z, wvv.w};
            float sv[4] = {wsv.x, wsv.y, wsv.z, wsv.w};
#pragma unroll
            for (int a = 0; a < 4; a++)
#pragma unroll
                for (int b = 0; b < 4; b++) {
                    a_ss[a][b] += h[a] * ss[b];
                    a_vv[a][b] += h[a] * vv[b];
                    a_sv[a][b] += h[a] * sv[b];
                }
        }
    }

    // ---- stage 3: messages + scatter ----
#pragma unroll
    for (int a = 0; a < 4; a++) {
        int e = el0 + a;
        int row = row_s[e];
        int col = col_s[e];
        float ddx = dir_s[e * 3 + 0], ddy = dir_s[e * 3 + 1], ddz = dir_s[e * 3 + 2];
        float4 sc4 = *(const float4*)&g_s[col * HID + j0];
        float scv[4] = {sc4.x, sc4.y, sc4.z, sc4.w};
        const float* vcb = &g_v[col * HID * 3 + j0 * 3];
        float4 v0 = *(const float4*)(vcb + 0);
        float4 v1 = *(const float4*)(vcb + 4);
        float4 v2 = *(const float4*)(vcb + 8);
        float vcv[12] = {v0.x, v0.y, v0.z, v0.w, v1.x, v1.y, v1.z, v1.w, v2.x, v2.y, v2.z, v2.w};
        float* msp = &g_ms[row * HID + j0];
        float* mvp = &g_mv[row * HID * 3 + j0 * 3];
#pragma unroll
        for (int b = 0; b < 4; b++) {
            float hss = a_ss[a][b] + b2[j0 + b];
            float hvv = a_vv[a][b] + b2[HID + j0 + b];
            float hsv = a_sv[a][b] + b2[2 * HID + j0 + b];
            atomicAdd(msp + b, hss * scv[b]);
            float cc = hsv * scv[b];
            atomicAdd(mvp + b * 3 + 0, hvv * vcv[b * 3 + 0] + cc * ddx);
            atomicAdd(mvp + b * 3 + 1, hvv * vcv[b * 3 + 1] + cc * ddy);
            atomicAdd(mvp + b * 3 + 2, hvv * vcv[b * 3 + 2] + cc * ddz);
        }
    }
}

// ---------------- node update kernel (per layer) ----------------
// 64-node tile, 512 threads.
// x = [s | m_s | ||m_v||]  (64 x 384) in smem
// t = silu(x @ uW1 + b1)   (64 x 128)
// u = t @ uW2 + b2         (64 x 384) -> delta_s, alpha, beta
// s += delta_s ; v = alpha*v + beta*m_v ; zero m_s/m_v for next layer
#define NT 64
// smem float layout:
//  xs  : [0, 24832)        64 x 388   (w2 chunk 32x384 overlaps after stage1)
//  w1c : [24832, 28928)    32 x 128
//  ts  : [28928, 37376)    64 x 132
#define NODE_SMEM_FLOATS 37376

extern "C" __global__ void __launch_bounds__(512, 1)
node_kernel(int layer,
            const float* __restrict__ uW1, const float* __restrict__ ub1,
            const float* __restrict__ uW2, const float* __restrict__ ub2) {
    extern __shared__ float sm[];
    float* xs = sm;              // [64][388]
    float* w1c = sm + 24832;     // [32][128]
    float* ts = sm + 28928;      // [64][132]
    float* w2c = sm;             // [32][384] overlaps xs in stage2

    const int tid = threadIdx.x;
    const int n0 = blockIdx.x * NT;
    const float* W1 = uW1 + layer * 384 * HID;
    const float* b1 = ub1 + layer * HID;
    const float* W2 = uW2 + layer * HID * 384;
    const float* b2 = ub2 + layer * 384;

    // fill x tile; consume + zero m_s
    for (int idx = tid; idx < NT * HID; idx += 512) {
        int n = idx >> 7;
        int j = idx & 127;
        int gn = n0 + n;
        float sv = 0.f, msv = 0.f, vn = 0.f;
        if (gn < N_ATOMS) {
            sv = g_s[gn * HID + j];
            msv = g_ms[gn * HID + j];
            g_ms[gn * HID + j] = 0.f;
            int vb = (gn * HID + j) * 3;
            float mx = g_mv[vb + 0], my = g_mv[vb + 1], mz = g_mv[vb + 2];
            vn = sqrtf(mx * mx + my * my + mz * mz);
        }
        xs[n * 388 + j] = sv;
        xs[n * 388 + HID + j] = msv;
        xs[n * 388 + 2 * HID + j] = vn;
    }
    __syncthreads();

    const int jg = tid & 31;
    const int ng = tid >> 5;
    const int j0 = jg * 4;
    const int nl0 = ng * 4;

    // ---- stage 1: t = silu(x @ W1 + b1) ----
    float tacc[4][4];
#pragma unroll
    for (int a = 0; a < 4; a++)
#pragma unroll
        for (int b = 0; b < 4; b++) tacc[a][b] = b1[j0 + b];

    for (int kc = 0; kc < 384; kc += 32) {
        for (int idx = tid; idx < 32 * HID; idx += 512) w1c[idx] = W1[kc * HID + idx];
        __syncthreads();
#pragma unroll 8
        for (int kk = 0; kk < 32; kk++) {
            float x[4];
#pragma unroll
            for (int a = 0; a < 4; a++) x[a] = xs[(nl0 + a) * 388 + kc + kk];
            float4 w = *(const float4*)&w1c[kk * HID + j0];
            float wv[4] = {w.x, w.y, w.z, w.w};
#pragma unroll
            for (int a = 0; a < 4; a++)
#pragma unroll
                for (int b = 0; b < 4; b++) tacc[a][b] += x[a] * wv[b];
        }
        __syncthreads();
    }
#pragma unroll
    for (int a = 0; a < 4; a++)
#pragma unroll
        for (int b = 0; b < 4; b++) ts[(nl0 + a) * 132 + j0 + b] = silu_f(tacc[a][b]);
    __syncthreads();

    // ---- stage 2: u = t @ W2 + b2 ----
    float a_d[4][4], a_a[4][4], a_b[4][4];
#pragma unroll
    for (int a = 0; a < 4; a++)
#pragma unroll
        for (int b = 0; b < 4; b++) { a_d[a][b] = 0.f; a_a[a][b] = 0.f; a_b[a][b] = 0.f; }

    for (int kc = 0; kc < HID; kc += 32) {
        for (int idx = tid; idx < 32 * 384; idx += 512) w2c[idx] = W2[kc * 384 + idx];
        __syncthreads();
#pragma unroll 8
        for (int kk = 0; kk < 32; kk++) {
            float t[4];
#pragma unroll
            for (int a = 0; a < 4; a++) t[a] = ts[(nl0 + a) * 132 + kc + kk];
            float4 wd = *(const float4*)&w2c[kk * 384 + j0];
            float4 wa = *(const float4*)&w2c[kk * 384 + 128 + j0];
            float4 wb = *(const float4*)&w2c[kk * 384 + 256 + j0];
            float dv[4] = {wd.x, wd.y, wd.z, wd.w};
            float av[4] = {wa.x, wa.y, wa.z, wa.w};
            float bv[4] = {wb.x, wb.y, wb.z, wb.w};
#pragma unroll
            for (int a = 0; a < 4; a++)
#pragma unroll
                for (int b = 0; b < 4; b++) {
                    a_d[a][b] += t[a] * dv[b];
                    a_a[a][b] += t[a] * av[b];
                    a_b[a][b] += t[a] * bv[b];
                }
        }
        __syncthreads();
    }

    // ---- update s, v; zero m_v ----
#pragma unroll
    for (int a = 0; a < 4; a++) {
        int gn = n0 + nl0 + a;
        if (gn < N_ATOMS) {
#pragma unroll
            for (int b = 0; b < 4; b++) {
                int j = j0 + b;
                float ds = a_d[a][b] + b2[j];
                float al = a_a[a][b] + b2[HID + j];
                float be = a_b[a][b] + b2[2 * HID + j];
                g_s[gn * HID + j] += ds;
                int vb = (gn * HID + j) * 3;
#pragma unroll
                for (int d = 0; d < 3; d++) {
                    float mv = g_mv[vb + d];
                    g_v[vb + d] = al * g_v[vb + d] + be * mv;
                    g_mv[vb + d] = 0.f;
                }
            }
        }
    }
}

// ---------------- molecule pooling + heads ----------------
__global__ void pool_zero_kernel() {
    int idx = blockIdx.x * blockDim.x + threadIdx.x;
    if (idx < N_MOLS * HID) g_hmol[idx] = 0.f;
    if (idx < N_MOLS) g_cnt[idx] = 0.f;
}

__global__ void pool_acc_kernel(const int* __restrict__ batch) {
    int idx = blockIdx.x * blockDim.x + threadIdx.x;
    if (idx >= N_ATOMS * HID) return;
    int n = idx >> 7;
    int j = idx & 127;
    int m = batch[n];
    atomicAdd(&g_hmol[m * HID + j], g_s[idx]);
    if (j == 0) atomicAdd(&g_cnt[m], 1.0f);
}

__global__ void head_kernel(const float* __restrict__ lW1, const float* __restrict__ lb1,
                            const float* __restrict__ lW2, const float* __restrict__ lb2,
                            const float* __restrict__ pW1, const float* __restrict__ pb1,
                            const float* __restrict__ pW2, const float* __restrict__ pb2,
                            float* __restrict__ out) {
    __shared__ float hm[HID];
    __shared__ float tt[HID];
    __shared__ float red[HID];
    int m = blockIdx.x;
    int j = threadIdx.x;
    float cnt = g_cnt[m];
    hm[j] = g_hmol[m * HID + j] / cnt;
    __syncthreads();

    // lam head
    float acc = lb1[j];
    for (int k = 0; k < HID; k++) acc += hm[k] * lW1[k * HID + j];
    tt[j] = silu_f(acc);
    __syncthreads();
    red[j] = tt[j] * lW2[j];
    __syncthreads();
    for (int s = 64; s > 0; s >>= 1) {
        if (j < s) red[j] += red[j + s];
        __syncthreads();
    }
    if (j == 0) out[m] = red[0] + lb2[0];
    __syncthreads();

    // phi head
    acc = pb1[j];
    for (int k = 0; k < HID; k++) acc += hm[k] * pW1[k * HID + j];
    tt[j] = silu_f(acc);
    __syncthreads();
    red[j] = tt[j] * pW2[j];
    __syncthreads();
    for (int s = 64; s > 0; s >>= 1) {
        if (j < s) red[j] += red[j + s];
        __syncthreads();
    }
    if (j == 0) {
        float x = red[0] + pb2[0];
        out[N_MOLS + m] = 1.0f / (1.0f + expf(-x));
    }
}

// ---------------- launch ----------------
extern "C" void kernel_launch(void* const* d_in, const int* in_sizes, int n_in,
                              void* d_out, int out_size) {
    const int* z = (const int*)d_in[0];
    const float* pos = (const float*)d_in[1];
    const int* ei = (const int*)d_in[2];
    const int* batch = (const int*)d_in[3];
    const float* emb = (const float*)d_in[4];
    const float* fW1 = (const float*)d_in[5];
    const float* fb1 = (const float*)d_in[6];
    const float* fW2 = (const float*)d_in[7];
    const float* fb2 = (const float*)d_in[8];
    const float* uW1 = (const float*)d_in[9];
    const float* ub1 = (const float*)d_in[10];
    const float* uW2 = (const float*)d_in[11];
    const float* ub2 = (const float*)d_in[12];
    const float* lW1 = (const float*)d_in[13];
    const float* lb1 = (const float*)d_in[14];
    const float* lW2 = (const float*)d_in[15];
    const float* lb2 = (const float*)d_in[16];
    const float* pW1 = (const float*)d_in[17];
    const float* pb1 = (const float*)d_in[18];
    const float* pW2 = (const float*)d_in[19];
    const float* pb2 = (const float*)d_in[20];
    float* out = (float*)d_out;

    cudaFuncSetAttribute(edge_kernel, cudaFuncAttributeMaxDynamicSharedMemorySize,
                         EDGE_SMEM_FLOATS * 4);
    cudaFuncSetAttribute(node_kernel, cudaFuncAttributeMaxDynamicSharedMemorySize,
                         NODE_SMEM_FLOATS * 4);

    geom_kernel<<<(N_EDGES + 255) / 256, 256>>>(pos, ei);
    init_kernel<<<(N_ATOMS * HID + 255) / 256, 256>>>(z, emb);

    for (int layer = 0; layer < NLAYERS; layer++) {
        edge_kernel<<<N_EDGES / ET, 512, EDGE_SMEM_FLOATS * 4>>>(layer, ei, fW1, fb1, fW2, fb2);
        node_kernel<<<(N_ATOMS + NT - 1) / NT, 512, NODE_SMEM_FLOATS * 4>>>(layer, uW1, ub1, uW2, ub2);
    }

    pool_zero_kernel<<<(N_MOLS * HID + 255) / 256, 256>>>();
    pool_acc_kernel<<<(N_ATOMS * HID + 255) / 256, 256>>>(batch);
    head_kernel<<<N_MOLS, HID>>>(lW1, lb1, lW2, lb2, pW1, pb1, pW2, pb2, out);
}

// round 3
// speedup vs baseline: 2.2468x; 2.2468x over previous
#include <cuda_runtime.h>
#include <math.h>

#define N_ATOMS 50000
#define N_EDGES 400000
#define N_MOLS  500
#define HID     128
#define NRBF    20
#define NLAYERS 4
#define NV      (N_ATOMS * HID)

#define TAB_D   8192
#define TAB_MAX 12.0f
#define RBF_STEP (5.0f / (float)(NRBF - 1))

// ---------------- device scratch ----------------
__device__ float g_dist[N_EDGES];
__device__ float g_dir[N_EDGES * 3];
__device__ float g_s[NV];
__device__ float g_v[3 * NV];    // planar [3][N][HID]
__device__ float g_ms[NV];
__device__ float g_mv[3 * NV];   // planar [3][N][HID]
__device__ float g_htab[NLAYERS * TAB_D * 3 * HID];
__device__ float g_hmol[N_MOLS * HID];
__device__ float g_cnt[N_MOLS];

__device__ __forceinline__ float silu_f(float x) { return x / (1.0f + expf(-x)); }

// ---------------- geometry ----------------
__global__ void geom_kernel(const float* __restrict__ pos, const int* __restrict__ ei) {
    int e = blockIdx.x * blockDim.x + threadIdx.x;
    if (e >= N_EDGES) return;
    int r = ei[e];
    int c = ei[N_EDGES + e];
    float dx = pos[c * 3 + 0] - pos[r * 3 + 0];
    float dy = pos[c * 3 + 1] - pos[r * 3 + 1];
    float dz = pos[c * 3 + 2] - pos[r * 3 + 2];
    float dist = sqrtf(dx * dx + dy * dy + dz * dz);
    float inv = 1.0f / (dist + 1e-8f);
    g_dist[e] = dist;
    g_dir[e * 3 + 0] = dx * inv;
    g_dir[e * 3 + 1] = dy * inv;
    g_dir[e * 3 + 2] = dz * inv;
}

// ---------------- init ----------------
__global__ void init_kernel(const int* __restrict__ z, const float* __restrict__ emb) {
    int idx = blockIdx.x * blockDim.x + threadIdx.x;
    if (idx >= NV) return;
    int n = idx >> 7;
    int j = idx & 127;
    g_s[idx] = emb[z[n] * HID + j];
    g_ms[idx] = 0.0f;
    g_v[idx] = 0.0f; g_v[NV + idx] = 0.0f; g_v[2 * NV + idx] = 0.0f;
    g_mv[idx] = 0.0f; g_mv[NV + idx] = 0.0f; g_mv[2 * NV + idx] = 0.0f;
}

// ---------------- filter table build ----------------
#define TAB_SMEM_FLOATS 20736

extern "C" __global__ void __launch_bounds__(512, 1)
table_kernel(const float* __restrict__ fW1, const float* __restrict__ fb1,
             const float* __restrict__ fW2, const float* __restrict__ fb2) {
    extern __shared__ float sm[];
    float* hid = sm;                 // [64][132]
    float* rbf_s = sm + 8448;        // [64][20]
    float* w1_s = sm + 9728;         // [20][128]
    float* w2_s = sm + 8448;         // [32][384] (stage2, overlaps)

    const int tid = threadIdx.x;
    const int layer = blockIdx.y;
    const int g0 = blockIdx.x * 64;
    const float* W1 = fW1 + layer * NRBF * HID;
    const float* b1 = fb1 + layer * HID;
    const float* W2 = fW2 + layer * HID * 3 * HID;
    const float* b2 = fb2 + layer * 3 * HID;
    const float DELTA = TAB_MAX / (float)(TAB_D - 1);

    for (int idx = tid; idx < 64 * NRBF; idx += 512) {
        int e = idx / NRBF, k = idx % NRBF;
        float d = (float)(g0 + e) * DELTA - RBF_STEP * (float)k;
        rbf_s[idx] = expf(-d * d);
    }
    for (int idx = tid; idx < NRBF * HID; idx += 512) w1_s[idx] = W1[idx];
    __syncthreads();

    const int jg = tid & 31;
    const int eg = tid >> 5;
    const int j0 = jg * 4;
    const int el0 = eg * 4;

    float hacc[4][4];
#pragma unroll
    for (int a = 0; a < 4; a++)
#pragma unroll
        for (int b = 0; b < 4; b++) hacc[a][b] = b1[j0 + b];
#pragma unroll
    for (int k = 0; k < NRBF; k++) {
        float r[4];
#pragma unroll
        for (int a = 0; a < 4; a++) r[a] = rbf_s[(el0 + a) * NRBF + k];
        float4 w = *(const float4*)&w1_s[k * HID + j0];
        float wv[4] = {w.x, w.y, w.z, w.w};
#pragma unroll
        for (int a = 0; a < 4; a++)
#pragma unroll
            for (int b = 0; b < 4; b++) hacc[a][b] += r[a] * wv[b];
    }
#pragma unroll
    for (int a = 0; a < 4; a++)
#pragma unroll
        for (int b = 0; b < 4; b++) hid[(el0 + a) * 132 + j0 + b] = silu_f(hacc[a][b]);
    __syncthreads();

    float a_ss[4][4], a_vv[4][4], a_sv[4][4];
#pragma unroll
    for (int a = 0; a < 4; a++)
#pragma unroll
        for (int b = 0; b < 4; b++) { a_ss[a][b] = 0.f; a_vv[a][b] = 0.f; a_sv[a][b] = 0.f; }

    for (int kc = 0; kc < HID; kc += 32) {
        __syncthreads();
        for (int idx = tid; idx < 32 * 384; idx += 512) w2_s[idx] = W2[kc * 384 + idx];
        __syncthreads();
#pragma unroll 8
        for (int kk = 0; kk < 32; kk++) {
            float h[4];
#pragma unroll
            for (int a = 0; a < 4; a++) h[a] = hid[(el0 + a) * 132 + kc + kk];
            float4 wss = *(const float4*)&w2_s[kk * 384 + j0];
            float4 wvv = *(const float4*)&w2_s[kk * 384 + 128 + j0];
            float4 wsv = *(const float4*)&w2_s[kk * 384 + 256 + j0];
            float ss[4] = {wss.x, wss.y, wss.z, wss.w};
            float vv[4] = {wvv.x, wvv.y, wvv.z, wvv.w};
            float sv[4] = {wsv.x, wsv.y, wsv.z, wsv.w};
#pragma unroll
            for (int a = 0; a < 4; a++)
#pragma unroll
                for (int b = 0; b < 4; b++) {
                    a_ss[a][b] += h[a] * ss[b];
                    a_vv[a][b] += h[a] * vv[b];
                    a_sv[a][b] += h[a] * sv[b];
                }
        }
    }

#pragma unroll
    for (int a = 0; a < 4; a++) {
        int gi = g0 + el0 + a;
        float* T = g_htab + ((size_t)layer * TAB_D + gi) * 384;
#pragma unroll
        for (int b = 0; b < 4; b++) {
            T[j0 + b]       = a_ss[a][b] + b2[j0 + b];
            T[128 + j0 + b] = a_vv[a][b] + b2[128 + j0 + b];
            T[256 + j0 + b] = a_sv[a][b] + b2[256 + j0 + b];
        }
    }
}

// ---------------- edge message kernel (table lookup + scatter) ----------------
extern "C" __global__ void __launch_bounds__(256)
msg_kernel(int layer, const int* __restrict__ ei) {
    int w = (blockIdx.x * 256 + threadIdx.x) >> 5;
    int lane = threadIdx.x & 31;
    if (w >= N_EDGES) return;

    int row = __ldg(&ei[w]);
    int col = __ldg(&ei[N_EDGES + w]);
    float dist = g_dist[w];
    float dx = g_dir[3 * w + 0];
    float dy = g_dir[3 * w + 1];
    float dz = g_dir[3 * w + 2];

    const float INV_DELTA = (float)(TAB_D - 1) / TAB_MAX;
    float u = dist * INV_DELTA;
    int i0 = (int)u;
    if (i0 > TAB_D - 2) i0 = TAB_D - 2;
    float f = u - (float)i0;

    const float* T = g_htab + ((size_t)layer * TAB_D + i0) * 384;
    float hss[4], hvv[4], hsv[4], sc[4];
#pragma unroll
    for (int b = 0; b < 4; b++) {
        int j = lane + 32 * b;
        float a0 = T[j],        a1 = T[384 + j];
        float v0 = T[128 + j],  v1 = T[512 + j];
        float p0 = T[256 + j],  p1 = T[640 + j];
        hss[b] = a0 + f * (a1 - a0);
        hvv[b] = v0 + f * (v1 - v0);
        hsv[b] = p0 + f * (p1 - p0);
        sc[b] = g_s[col * HID + j];
    }
#pragma unroll
    for (int b = 0; b < 4; b++) {
        int j = lane + 32 * b;
        atomicAdd(&g_ms[row * HID + j], hss[b] * sc[b]);
    }
#pragma unroll
    for (int d = 0; d < 3; d++) {
        float dd = (d == 0) ? dx : ((d == 1) ? dy : dz);
        const float* vp = g_v + d * NV + col * HID;
        float* mp = g_mv + d * NV + row * HID;
#pragma unroll
        for (int b = 0; b < 4; b++) {
            int j = lane + 32 * b;
            float mv = hvv[b] * vp[j] + (hsv[b] * sc[b]) * dd;
            atomicAdd(&mp[j], mv);
        }
    }
}

// ---------------- node update kernel ----------------
// 64 nodes/block, 256 threads, 8x4 micro-tile, 2 CTAs/SM.
// Strides: xs_t/ts_t rows are 76 floats (multiple of 4 -> float4 aligned;
// A-operand reads are warp-uniform broadcasts so bank layout is irrelevant).
// smem floats: xs_t[64][76]=4864 @0 | wc[64][132]=8448 @4864 | ts_t[128][76]=9728 @13312
#define NT 64
#define XS_STRIDE 76
#define NODE_SMEM_FLOATS 23040

extern "C" __global__ void __launch_bounds__(256, 2)
node_kernel(int layer,
            const float* __restrict__ uW1, const float* __restrict__ ub1,
            const float* __restrict__ uW2, const float* __restrict__ ub2) {
    extern __shared__ float sm[];
    float* xs_t = sm;              // [64 k][76]
    float* wc   = sm + 4864;       // [64 k][132]
    float* ts_t = sm + 13312;      // [128 k][76]

    const int tid = threadIdx.x;
    const int n0 = blockIdx.x * NT;
    const float* W1 = uW1 + layer * 384 * HID;
    const float* b1 = ub1 + layer * HID;
    const float* W2 = uW2 + layer * HID * 384;
    const float* b2 = ub2 + layer * 384;

    const int og = tid & 31;
    const int ng = tid >> 5;
    const int j0 = og * 4;
    const int nl0 = ng * 8;

    // ---- stage 1: t = silu(x @ W1 + b1), x = [s | m_s | ||m_v||] ----
    float4 b1v = *(const float4*)&b1[j0];
    float acc[8][4];
#pragma unroll
    for (int a = 0; a < 8; a++) {
        acc[a][0] = b1v.x; acc[a][1] = b1v.y; acc[a][2] = b1v.z; acc[a][3] = b1v.w;
    }

    for (int kc = 0; kc < 384; kc += 64) {
        __syncthreads();
        for (int idx = tid; idx < 64 * 64; idx += 256) {
            int node = idx >> 6, k = idx & 63;
            int gk = kc + k, gn = n0 + node;
            float val = 0.f;
            if (gn < N_ATOMS) {
                if (gk < 128) {
                    val = g_s[gn * HID + gk];
                } else if (gk < 256) {
                    int p = gn * HID + (gk - 128);
                    val = g_ms[p];
                    g_ms[p] = 0.f;
                } else {
                    int p = gn * HID + (gk - 256);
                    float mx = g_mv[p], my = g_mv[NV + p], mz = g_mv[2 * NV + p];
                    val = sqrtf(mx * mx + my * my + mz * mz);
                }
            }
            xs_t[k * XS_STRIDE + node] = val;
        }
        for (int idx = tid; idx < 64 * 128; idx += 256) {
            int k = idx >> 7, j = idx & 127;
            wc[k * 132 + j] = W1[(kc + k) * HID + j];
        }
        __syncthreads();
#pragma unroll 4
        for (int kk = 0; kk < 64; kk++) {
            float4 a0 = *(const float4*)&xs_t[kk * XS_STRIDE + nl0];
            float4 a1 = *(const float4*)&xs_t[kk * XS_STRIDE + nl0 + 4];
            float4 w = *(const float4*)&wc[kk * 132 + j0];
            float av[8] = {a0.x, a0.y, a0.z, a0.w, a1.x, a1.y, a1.z, a1.w};
            float wv[4] = {w.x, w.y, w.z, w.w};
#pragma unroll
            for (int a = 0; a < 8; a++)
#pragma unroll
                for (int b = 0; b < 4; b++) acc[a][b] += av[a] * wv[b];
        }
    }
    __syncthreads();
#pragma unroll
    for (int a = 0; a < 8; a++)
#pragma unroll
        for (int b = 0; b < 4; b++) ts_t[(j0 + b) * XS_STRIDE + nl0 + a] = silu_f(acc[a][b]);

    // ---- stage 2: u = t @ W2 + b2, three 128-wide output blocks ----
    for (int jb = 0; jb < 3; jb++) {
        float u2[8][4];
#pragma unroll
        for (int a = 0; a < 8; a++)
#pragma unroll
            for (int b = 0; b < 4; b++) u2[a][b] = 0.f;

        for (int kc2 = 0; kc2 < 128; kc2 += 64) {
            __syncthreads();
            for (int idx = tid; idx < 64 * 128; idx += 256) {
                int k = idx >> 7, j = idx & 127;
                wc[k * 132 + j] = W2[(kc2 + k) * 384 + jb * 128 + j];
            }
            __syncthreads();
#pragma unroll 4
            for (int kk = 0; kk < 64; kk++) {
                float4 a0 = *(const float4*)&ts_t[(kc2 + kk) * XS_STRIDE + nl0];
                float4 a1 = *(const float4*)&ts_t[(kc2 + kk) * XS_STRIDE + nl0 + 4];
                float4 w = *(const float4*)&wc[kk * 132 + j0];
                float av[8] = {a0.x, a0.y, a0.z, a0.w, a1.x, a1.y, a1.z, a1.w};
                float wv[4] = {w.x, w.y, w.z, w.w};
#pragma unroll
                for (int a = 0; a < 8; a++)
#pragma unroll
                    for (int b = 0; b < 4; b++) u2[a][b] += av[a] * wv[b];
            }
        }

        float4 b2v = *(const float4*)&b2[jb * 128 + j0];
        float bb[4] = {b2v.x, b2v.y, b2v.z, b2v.w};
#pragma unroll
        for (int a = 0; a < 8; a++) {
            int gn = n0 + nl0 + a;
            if (gn >= N_ATOMS) continue;
            if (jb == 0) {
#pragma unroll
                for (int b = 0; b < 4; b++)
                    g_s[gn * HID + j0 + b] += u2[a][b] + bb[b];
            } else if (jb == 1) {
#pragma unroll
                for (int d = 0; d < 3; d++) {
                    float4* vp = (float4*)&g_v[d * NV + gn * HID + j0];
                    float4 vv = *vp;
                    vv.x *= (u2[a][0] + bb[0]);
                    vv.y *= (u2[a][1] + bb[1]);
                    vv.z *= (u2[a][2] + bb[2]);
                    vv.w *= (u2[a][3] + bb[3]);
                    *vp = vv;
                }
            } else {
#pragma unroll
                for (int d = 0; d < 3; d++) {
                    float4* vp = (float4*)&g_v[d * NV + gn * HID + j0];
                    float4* mp = (float4*)&g_mv[d * NV + gn * HID + j0];
                    float4 vv = *vp;
                    float4 mv = *mp;
                    vv.x += (u2[a][0] + bb[0]) * mv.x;
                    vv.y += (u2[a][1] + bb[1]) * mv.y;
                    vv.z += (u2[a][2] + bb[2]) * mv.z;
                    vv.w += (u2[a][3] + bb[3]) * mv.w;
                    *vp = vv;
                    *mp = make_float4(0.f, 0.f, 0.f, 0.f);
                }
            }
        }
    }
}

// ---------------- molecule pooling + heads ----------------
__global__ void pool_zero_kernel() {
    int idx = blockIdx.x * blockDim.x + threadIdx.x;
    if (idx < N_MOLS * HID) g_hmol[idx] = 0.f;
    if (idx < N_MOLS) g_cnt[idx] = 0.f;
}

__global__ void pool_acc_kernel(const int* __restrict__ batch) {
    int idx = blockIdx.x * blockDim.x + threadIdx.x;
    if (idx >= NV) return;
    int n = idx >> 7;
    int j = idx & 127;
    int m = batch[n];
    atomicAdd(&g_hmol[m * HID + j], g_s[idx]);
    if (j == 0) atomicAdd(&g_cnt[m], 1.0f);
}

__global__ void head_kernel(const float* __restrict__ lW1, const float* __restrict__ lb1,
                            const float* __restrict__ lW2, const float* __restrict__ lb2,
                            const float* __restrict__ pW1, const float* __restrict__ pb1,
                            const float* __restrict__ pW2, const float* __restrict__ pb2,
                            float* __restrict__ out) {
    __shared__ float hm[HID];
    __shared__ float tt[HID];
    __shared__ float red[HID];
    int m = blockIdx.x;
    int j = threadIdx.x;
    float cnt = g_cnt[m];
    hm[j] = g_hmol[m * HID + j] / cnt;
    __syncthreads();

    float acc = lb1[j];
    for (int k = 0; k < HID; k++) acc += hm[k] * lW1[k * HID + j];
    tt[j] = silu_f(acc);
    __syncthreads();
    red[j] = tt[j] * lW2[j];
    __syncthreads();
    for (int s = 64; s > 0; s >>= 1) {
        if (j < s) red[j] += red[j + s];
        __syncthreads();
    }
    if (j == 0) out[m] = red[0] + lb2[0];
    __syncthreads();

    acc = pb1[j];
    for (int k = 0; k < HID; k++) acc += hm[k] * pW1[k * HID + j];
    tt[j] = silu_f(acc);
    __syncthreads();
    red[j] = tt[j] * pW2[j];
    __syncthreads();
    for (int s = 64; s > 0; s >>= 1) {
        if (j < s) red[j] += red[j + s];
        __syncthreads();
    }
    if (j == 0) {
        float x = red[0] + pb2[0];
        out[N_MOLS + m] = 1.0f / (1.0f + expf(-x));
    }
}

// ---------------- launch ----------------
extern "C" void kernel_launch(void* const* d_in, const int* in_sizes, int n_in,
                              void* d_out, int out_size) {
    const int* z = (const int*)d_in[0];
    const float* pos = (const float*)d_in[1];
    const int* ei = (const int*)d_in[2];
    const int* batch = (const int*)d_in[3];
    const float* emb = (const float*)d_in[4];
    const float* fW1 = (const float*)d_in[5];
    const float* fb1 = (const float*)d_in[6];
    const float* fW2 = (const float*)d_in[7];
    const float* fb2 = (const float*)d_in[8];
    const float* uW1 = (const float*)d_in[9];
    const float* ub1 = (const float*)d_in[10];
    const float* uW2 = (const float*)d_in[11];
    const float* ub2 = (const float*)d_in[12];
    const float* lW1 = (const float*)d_in[13];
    const float* lb1 = (const float*)d_in[14];
    const float* lW2 = (const float*)d_in[15];
    const float* lb2 = (const float*)d_in[16];
    const float* pW1 = (const float*)d_in[17];
    const float* pb1 = (const float*)d_in[18];
    const float* pW2 = (const float*)d_in[19];
    const float* pb2 = (const float*)d_in[20];
    float* out = (float*)d_out;

    cudaFuncSetAttribute(table_kernel, cudaFuncAttributeMaxDynamicSharedMemorySize,
                         TAB_SMEM_FLOATS * 4);
    cudaFuncSetAttribute(node_kernel, cudaFuncAttributeMaxDynamicSharedMemorySize,
                         NODE_SMEM_FLOATS * 4);

    geom_kernel<<<(N_EDGES + 255) / 256, 256>>>(pos, ei);
    init_kernel<<<(NV + 255) / 256, 256>>>(z, emb);
    table_kernel<<<dim3(TAB_D / 64, NLAYERS), 512, TAB_SMEM_FLOATS * 4>>>(fW1, fb1, fW2, fb2);

    const int msg_blocks = (N_EDGES * 32 + 255) / 256;
    const int node_blocks = (N_ATOMS + NT - 1) / NT;
    for (int layer = 0; layer < NLAYERS; layer++) {
        msg_kernel<<<msg_blocks, 256>>>(layer, ei);
        node_kernel<<<node_blocks, 256, NODE_SMEM_FLOATS * 4>>>(layer, uW1, ub1, uW2, ub2);
    }

    pool_zero_kernel<<<(N_MOLS * HID + 255) / 256, 256>>>();
    pool_acc_kernel<<<(NV + 255) / 256, 256>>>(batch);
    head_kernel<<<N_MOLS, HID>>>(lW1, lb1, lW2, lb2, pW1, pb1, pW2, pb2, out);
}

// round 4
// speedup vs baseline: 4.0579x; 1.8061x over previous
#include <cuda_runtime.h>
#include <math.h>

#define N_ATOMS 50000
#define N_EDGES 400000
#define N_MOLS  500
#define HID     128
#define NRBF    20
#define NLAYERS 4
#define NV      (N_ATOMS * HID)

#define TAB_D   8192
#define TAB_MAX 12.0f
#define RBF_STEP (5.0f / (float)(NRBF - 1))

// ---------------- device scratch ----------------
__device__ float g_s[NV];
__device__ float g_v[3 * NV];    // planar [3][N][HID]
__device__ float g_ms[NV];
__device__ float g_mv[3 * NV];   // planar [3][N][HID]
__device__ float g_htab[NLAYERS * TAB_D * 3 * HID];
__device__ float g_hmol[N_MOLS * HID];
__device__ float g_cnt[N_MOLS];

// CSR scratch
__device__ int   g_deg[N_ATOMS];
__device__ int   g_rowptr[N_ATOMS + 1];
__device__ int   g_cursor[N_ATOMS];
__device__ int   g_bsum[128];
__device__ int   g_ecol[N_EDGES];
__device__ float4 g_egeo[N_EDGES];   // (dirx, diry, dirz, dist)

__device__ __forceinline__ float silu_f(float x) { return x / (1.0f + expf(-x)); }

// ---------------- init: s=emb[z], v=0, deg=0 ----------------
__global__ void init_kernel(const int* __restrict__ z, const float* __restrict__ emb) {
    int idx = blockIdx.x * blockDim.x + threadIdx.x;
    if (idx < N_ATOMS) g_deg[idx] = 0;
    if (idx >= NV) return;
    int n = idx >> 7;
    int j = idx & 127;
    g_s[idx] = emb[z[n] * HID + j];
    g_v[idx] = 0.0f; g_v[NV + idx] = 0.0f; g_v[2 * NV + idx] = 0.0f;
}

// ---------------- CSR build ----------------
__global__ void hist_kernel(const int* __restrict__ ei) {
    int e = blockIdx.x * blockDim.x + threadIdx.x;
    if (e >= N_EDGES) return;
    atomicAdd(&g_deg[ei[e]], 1);
}

#define SCAN_B 512
__global__ void scan1_kernel() {
    __shared__ int s[SCAN_B];
    int t = threadIdx.x;
    int i = blockIdx.x * SCAN_B + t;
    int v = (i < N_ATOMS) ? g_deg[i] : 0;
    s[t] = v;
    __syncthreads();
    for (int off = 1; off < SCAN_B; off <<= 1) {
        int add = (t >= off) ? s[t - off] : 0;
        __syncthreads();
        s[t] += add;
        __syncthreads();
    }
    if (i < N_ATOMS) g_rowptr[i] = s[t] - v;   // block-exclusive
    if (t == SCAN_B - 1) g_bsum[blockIdx.x] = s[t];
}

__global__ void scan2_kernel(int nblocks) {
    if (threadIdx.x == 0) {
        int run = 0;
        for (int b = 0; b < nblocks; b++) {
            int t = g_bsum[b];
            g_bsum[b] = run;
            run += t;
        }
    }
}

__global__ void scan3_kernel() {
    int i = blockIdx.x * blockDim.x + threadIdx.x;
    if (i < N_ATOMS) {
        int rp = g_rowptr[i] + g_bsum[i >> 9];
        g_rowptr[i] = rp;
        g_cursor[i] = rp;
    }
    if (i == 0) g_rowptr[N_ATOMS] = N_EDGES;
}

__global__ void scatter_kernel(const int* __restrict__ ei, const float* __restrict__ pos) {
    int e = blockIdx.x * blockDim.x + threadIdx.x;
    if (e >= N_EDGES) return;
    int r = ei[e];
    int c = ei[N_EDGES + e];
    float dx = pos[c * 3 + 0] - pos[r * 3 + 0];
    float dy = pos[c * 3 + 1] - pos[r * 3 + 1];
    float dz = pos[c * 3 + 2] - pos[r * 3 + 2];
    float dist = sqrtf(dx * dx + dy * dy + dz * dz);
    float inv = 1.0f / (dist + 1e-8f);
    int p = atomicAdd(&g_cursor[r], 1);
    g_ecol[p] = c;
    g_egeo[p] = make_float4(dx * inv, dy * inv, dz * inv, dist);
}

// ---------------- filter table build ----------------
#define TAB_SMEM_FLOATS 20736

extern "C" __global__ void __launch_bounds__(512, 1)
table_kernel(const float* __restrict__ fW1, const float* __restrict__ fb1,
             const float* __restrict__ fW2, const float* __restrict__ fb2) {
    extern __shared__ float sm[];
    float* hid = sm;                 // [64][132]
    float* rbf_s = sm + 8448;        // [64][20]
    float* w1_s = sm + 9728;         // [20][128]
    float* w2_s = sm + 8448;         // [32][384] (stage2, overlaps)

    const int tid = threadIdx.x;
    const int layer = blockIdx.y;
    const int g0 = blockIdx.x * 64;
    const float* W1 = fW1 + layer * NRBF * HID;
    const float* b1 = fb1 + layer * HID;
    const float* W2 = fW2 + layer * HID * 3 * HID;
    const float* b2 = fb2 + layer * 3 * HID;
    const float DELTA = TAB_MAX / (float)(TAB_D - 1);

    for (int idx = tid; idx < 64 * NRBF; idx += 512) {
        int e = idx / NRBF, k = idx % NRBF;
        float d = (float)(g0 + e) * DELTA - RBF_STEP * (float)k;
        rbf_s[idx] = expf(-d * d);
    }
    for (int idx = tid; idx < NRBF * HID; idx += 512) w1_s[idx] = W1[idx];
    __syncthreads();

    const int jg = tid & 31;
    const int eg = tid >> 5;
    const int j0 = jg * 4;
    const int el0 = eg * 4;

    float hacc[4][4];
#pragma unroll
    for (int a = 0; a < 4; a++)
#pragma unroll
        for (int b = 0; b < 4; b++) hacc[a][b] = b1[j0 + b];
#pragma unroll
    for (int k = 0; k < NRBF; k++) {
        float r[4];
#pragma unroll
        for (int a = 0; a < 4; a++) r[a] = rbf_s[(el0 + a) * NRBF + k];
        float4 w = *(const float4*)&w1_s[k * HID + j0];
        float wv[4] = {w.x, w.y, w.z, w.w};
#pragma unroll
        for (int a = 0; a < 4; a++)
#pragma unroll
            for (int b = 0; b < 4; b++) hacc[a][b] += r[a] * wv[b];
    }
#pragma unroll
    for (int a = 0; a < 4; a++)
#pragma unroll
        for (int b = 0; b < 4; b++) hid[(el0 + a) * 132 + j0 + b] = silu_f(hacc[a][b]);
    __syncthreads();

    float a_ss[4][4], a_vv[4][4], a_sv[4][4];
#pragma unroll
    for (int a = 0; a < 4; a++)
#pragma unroll
        for (int b = 0; b < 4; b++) { a_ss[a][b] = 0.f; a_vv[a][b] = 0.f; a_sv[a][b] = 0.f; }

    for (int kc = 0; kc < HID; kc += 32) {
        __syncthreads();
        for (int idx = tid; idx < 32 * 384; idx += 512) w2_s[idx] = W2[kc * 384 + idx];
        __syncthreads();
#pragma unroll 8
        for (int kk = 0; kk < 32; kk++) {
            float h[4];
#pragma unroll
            for (int a = 0; a < 4; a++) h[a] = hid[(el0 + a) * 132 + kc + kk];
            float4 wss = *(const float4*)&w2_s[kk * 384 + j0];
            float4 wvv = *(const float4*)&w2_s[kk * 384 + 128 + j0];
            float4 wsv = *(const float4*)&w2_s[kk * 384 + 256 + j0];
            float ss[4] = {wss.x, wss.y, wss.z, wss.w};
            float vv[4] = {wvv.x, wvv.y, wvv.z, wvv.w};
            float sv[4] = {wsv.x, wsv.y, wsv.z, wsv.w};
#pragma unroll
            for (int a = 0; a < 4; a++)
#pragma unroll
                for (int b = 0; b < 4; b++) {
                    a_ss[a][b] += h[a] * ss[b];
                    a_vv[a][b] += h[a] * vv[b];
                    a_sv[a][b] += h[a] * sv[b];
                }
        }
    }

#pragma unroll
    for (int a = 0; a < 4; a++) {
        int gi = g0 + el0 + a;
        float* T = g_htab + ((size_t)layer * TAB_D + gi) * 384;
#pragma unroll
        for (int b = 0; b < 4; b++) {
            T[j0 + b]       = a_ss[a][b] + b2[j0 + b];
            T[128 + j0 + b] = a_vv[a][b] + b2[128 + j0 + b];
            T[256 + j0 + b] = a_sv[a][b] + b2[256 + j0 + b];
        }
    }
}

// ---------------- edge message kernel: CSR segment-sum, warp per row ----------------
extern "C" __global__ void __launch_bounds__(256)
msg_kernel(int layer) {
    int r = (blockIdx.x * 256 + threadIdx.x) >> 5;
    int lane = threadIdx.x & 31;
    if (r >= N_ATOMS) return;

    int beg = g_rowptr[r];
    int end = g_rowptr[r + 1];

    const float INV_DELTA = (float)(TAB_D - 1) / TAB_MAX;
    const float* Tl = g_htab + (size_t)layer * TAB_D * 384;

    float accS[4] = {0.f, 0.f, 0.f, 0.f};
    float accV[12];
#pragma unroll
    for (int q = 0; q < 12; q++) accV[q] = 0.f;

    for (int p = beg; p < end; p++) {
        int col = g_ecol[p];
        float4 geo = g_egeo[p];
        float u = geo.w * INV_DELTA;
        int i0 = (int)u;
        if (i0 > TAB_D - 2) i0 = TAB_D - 2;
        float f = u - (float)i0;
        const float* T = Tl + (size_t)i0 * 384;

#pragma unroll
        for (int b = 0; b < 4; b++) {
            int j = lane + 32 * b;
            float a0 = T[j],        a1 = T[384 + j];
            float v0 = T[128 + j],  v1 = T[512 + j];
            float p0 = T[256 + j],  p1 = T[640 + j];
            float hss = a0 + f * (a1 - a0);
            float hvv = v0 + f * (v1 - v0);
            float hsv = p0 + f * (p1 - p0);
            float sc = g_s[col * HID + j];
            accS[b] += hss * sc;
            float cc = hsv * sc;
            accV[b]     += hvv * g_v[col * HID + j]          + cc * geo.x;
            accV[4 + b] += hvv * g_v[NV + col * HID + j]     + cc * geo.y;
            accV[8 + b] += hvv * g_v[2 * NV + col * HID + j] + cc * geo.z;
        }
    }

#pragma unroll
    for (int b = 0; b < 4; b++) {
        int j = lane + 32 * b;
        g_ms[r * HID + j] = accS[b];
        g_mv[r * HID + j] = accV[b];
        g_mv[NV + r * HID + j] = accV[4 + b];
        g_mv[2 * NV + r * HID + j] = accV[8 + b];
    }
}

// ---------------- node update kernel ----------------
// 64 nodes/block, 256 threads, 8x4 micro-tile, 2 CTAs/SM, register-prefetched weights.
// smem floats: xs_t[64][76]=4864 @0 | wc[64][128]=8192 @4864 | ts_t[128][76]=9728 @13056
#define NT 64
#define XS_STRIDE 76
#define NODE_SMEM_FLOATS 22784

extern "C" __global__ void __launch_bounds__(256, 2)
node_kernel(int layer,
            const float* __restrict__ uW1, const float* __restrict__ ub1,
            const float* __restrict__ uW2, const float* __restrict__ ub2) {
    extern __shared__ float sm[];
    float* xs_t = sm;              // [64 k][76]
    float* wc   = sm + 4864;       // [64 k][128]
    float* ts_t = sm + 13056;      // [128 k][76]

    const int tid = threadIdx.x;
    const int n0 = blockIdx.x * NT;
    const float* W1 = uW1 + layer * 384 * HID;
    const float* b1 = ub1 + layer * HID;
    const float* W2 = uW2 + layer * HID * 384;
    const float* b2 = ub2 + layer * 384;

    const int og = tid & 31;
    const int ng = tid >> 5;
    const int j0 = og * 4;
    const int nl0 = ng * 8;

    // weight prefetch registers: chunk = 64 rows x 128 cols = 2048 float4
    const int pr_k = (tid * 4 + 0) >> 7;   // base for q=0... recompute per q below
    float4 wreg[8];

    // ---- prefetch W1 chunk 0 ----
#pragma unroll
    for (int q = 0; q < 8; q++) {
        int idx = q * 256 + tid;           // [0,2048)
        int k = idx >> 5, c4 = idx & 31;
        wreg[q] = *(const float4*)&W1[k * HID + c4 * 4];
    }
    (void)pr_k;

    // ---- stage 1: t = silu(x @ W1 + b1), x = [s | m_s | ||m_v||] ----
    float4 b1v = *(const float4*)&b1[j0];
    float acc[8][4];
#pragma unroll
    for (int a = 0; a < 8; a++) {
        acc[a][0] = b1v.x; acc[a][1] = b1v.y; acc[a][2] = b1v.z; acc[a][3] = b1v.w;
    }

    for (int kc = 0; kc < 384; kc += 64) {
        __syncthreads();
        // store prefetched weights
#pragma unroll
        for (int q = 0; q < 8; q++) {
            int idx = q * 256 + tid;
            int k = idx >> 5, c4 = idx & 31;
            *(float4*)&wc[k * 128 + c4 * 4] = wreg[q];
        }
        // stage x^T chunk
        for (int idx = tid; idx < 64 * 64; idx += 256) {
            int node = idx >> 6, k = idx & 63;
            int gk = kc + k, gn = n0 + node;
            float val = 0.f;
            if (gn < N_ATOMS) {
                if (gk < 128) {
                    val = g_s[gn * HID + gk];
                } else if (gk < 256) {
                    val = g_ms[gn * HID + (gk - 128)];
                } else {
                    int p = gn * HID + (gk - 256);
                    float mx = g_mv[p], my = g_mv[NV + p], mz = g_mv[2 * NV + p];
                    val = sqrtf(mx * mx + my * my + mz * mz);
                }
            }
            xs_t[k * XS_STRIDE + node] = val;
        }
        __syncthreads();
        // prefetch next W1 chunk (latency hidden under compute)
        if (kc + 64 < 384) {
#pragma unroll
            for (int q = 0; q < 8; q++) {
                int idx = q * 256 + tid;
                int k = idx >> 5, c4 = idx & 31;
                wreg[q] = *(const float4*)&W1[(kc + 64 + k) * HID + c4 * 4];
            }
        } else {
            // prefetch first W2 chunk (jb=0, kc2=0)
#pragma unroll
            for (int q = 0; q < 8; q++) {
                int idx = q * 256 + tid;
                int k = idx >> 5, c4 = idx & 31;
                wreg[q] = *(const float4*)&W2[k * 384 + c4 * 4];
            }
        }
#pragma unroll 4
        for (int kk = 0; kk < 64; kk++) {
            float4 a0 = *(const float4*)&xs_t[kk * XS_STRIDE + nl0];
            float4 a1 = *(const float4*)&xs_t[kk * XS_STRIDE + nl0 + 4];
            float4 w = *(const float4*)&wc[kk * 128 + j0];
            float av[8] = {a0.x, a0.y, a0.z, a0.w, a1.x, a1.y, a1.z, a1.w};
            float wv[4] = {w.x, w.y, w.z, w.w};
#pragma unroll
            for (int a = 0; a < 8; a++)
#pragma unroll
                for (int b = 0; b < 4; b++) acc[a][b] += av[a] * wv[b];
        }
    }
#pragma unroll
    for (int a = 0; a < 8; a++)
#pragma unroll
        for (int b = 0; b < 4; b++) ts_t[(j0 + b) * XS_STRIDE + nl0 + a] = silu_f(acc[a][b]);

    // ---- stage 2: u = t @ W2 + b2, 6 chunks: c -> (jb = c>>1, kc2 = (c&1)*64) ----
    float u2[8][4];
    for (int c = 0; c < 6; c++) {
        int jb = c >> 1;
        int kc2 = (c & 1) * 64;
        if (kc2 == 0) {
#pragma unroll
            for (int a = 0; a < 8; a++)
#pragma unroll
                for (int b = 0; b < 4; b++) u2[a][b] = 0.f;
        }
        __syncthreads();   // wc free; also (c==0) orders ts_t writes
#pragma unroll
        for (int q = 0; q < 8; q++) {
            int idx = q * 256 + tid;
            int k = idx >> 5, c4 = idx & 31;
            *(float4*)&wc[k * 128 + c4 * 4] = wreg[q];
        }
        __syncthreads();
        if (c < 5) {
            int cn = c + 1;
            int jbn = cn >> 1;
            int kc2n = (cn & 1) * 64;
#pragma unroll
            for (int q = 0; q < 8; q++) {
                int idx = q * 256 + tid;
                int k = idx >> 5, c4 = idx & 31;
                wreg[q] = *(const float4*)&W2[(kc2n + k) * 384 + jbn * 128 + c4 * 4];
            }
        }
#pragma unroll 4
        for (int kk = 0; kk < 64; kk++) {
            float4 a0 = *(const float4*)&ts_t[(kc2 + kk) * XS_STRIDE + nl0];
            float4 a1 = *(const float4*)&ts_t[(kc2 + kk) * XS_STRIDE + nl0 + 4];
            float4 w = *(const float4*)&wc[kk * 128 + j0];
            float av[8] = {a0.x, a0.y, a0.z, a0.w, a1.x, a1.y, a1.z, a1.w};
            float wv[4] = {w.x, w.y, w.z, w.w};
#pragma unroll
            for (int a = 0; a < 8; a++)
#pragma unroll
                for (int b = 0; b < 4; b++) u2[a][b] += av[a] * wv[b];
        }

        if (kc2 == 64) {
            // epilogue for this jb
            float4 b2v = *(const float4*)&b2[jb * 128 + j0];
            float bb[4] = {b2v.x, b2v.y, b2v.z, b2v.w};
#pragma unroll
            for (int a = 0; a < 8; a++) {
                int gn = n0 + nl0 + a;
                if (gn >= N_ATOMS) continue;
                if (jb == 0) {
#pragma unroll
                    for (int b = 0; b < 4; b++)
                        g_s[gn * HID + j0 + b] += u2[a][b] + bb[b];
                } else if (jb == 1) {
#pragma unroll
                    for (int d = 0; d < 3; d++) {
                        float4* vp = (float4*)&g_v[d * NV + gn * HID + j0];
                        float4 vv = *vp;
                        vv.x *= (u2[a][0] + bb[0]);
                        vv.y *= (u2[a][1] + bb[1]);
                        vv.z *= (u2[a][2] + bb[2]);
                        vv.w *= (u2[a][3] + bb[3]);
                        *vp = vv;
                    }
                } else {
#pragma unroll
                    for (int d = 0; d < 3; d++) {
                        float4* vp = (float4*)&g_v[d * NV + gn * HID + j0];
                        const float4* mp = (const float4*)&g_mv[d * NV + gn * HID + j0];
                        float4 vv = *vp;
                        float4 mv = *mp;
                        vv.x += (u2[a][0] + bb[0]) * mv.x;
                        vv.y += (u2[a][1] + bb[1]) * mv.y;
                        vv.z += (u2[a][2] + bb[2]) * mv.z;
                        vv.w += (u2[a][3] + bb[3]) * mv.w;
                        *vp = vv;
                    }
                }
            }
        }
    }
}

// ---------------- molecule pooling + heads ----------------
__global__ void pool_zero_kernel() {
    int idx = blockIdx.x * blockDim.x + threadIdx.x;
    if (idx < N_MOLS * HID) g_hmol[idx] = 0.f;
    if (idx < N_MOLS) g_cnt[idx] = 0.f;
}

__global__ void pool_acc_kernel(const int* __restrict__ batch) {
    int idx = blockIdx.x * blockDim.x + threadIdx.x;
    if (idx >= NV) return;
    int n = idx >> 7;
    int j = idx & 127;
    int m = batch[n];
    atomicAdd(&g_hmol[m * HID + j], g_s[idx]);
    if (j == 0) atomicAdd(&g_cnt[m], 1.0f);
}

__global__ void head_kernel(const float* __restrict__ lW1, const float* __restrict__ lb1,
                            const float* __restrict__ lW2, const float* __restrict__ lb2,
                            const float* __restrict__ pW1, const float* __restrict__ pb1,
                            const float* __restrict__ pW2, const float* __restrict__ pb2,
                            float* __restrict__ out) {
    __shared__ float hm[HID];
    __shared__ float tt[HID];
    __shared__ float red[HID];
    int m = blockIdx.x;
    int j = threadIdx.x;
    float cnt = g_cnt[m];
    hm[j] = g_hmol[m * HID + j] / cnt;
    __syncthreads();

    float acc = lb1[j];
    for (int k = 0; k < HID; k++) acc += hm[k] * lW1[k * HID + j];
    tt[j] = silu_f(acc);
    __syncthreads();
    red[j] = tt[j] * lW2[j];
    __syncthreads();
    for (int s = 64; s > 0; s >>= 1) {
        if (j < s) red[j] += red[j + s];
        __syncthreads();
    }
    if (j == 0) out[m] = red[0] + lb2[0];
    __syncthreads();

    acc = pb1[j];
    for (int k = 0; k < HID; k++) acc += hm[k] * pW1[k * HID + j];
    tt[j] = silu_f(acc);
    __syncthreads();
    red[j] = tt[j] * pW2[j];
    __syncthreads();
    for (int s = 64; s > 0; s >>= 1) {
        if (j < s) red[j] += red[j + s];
        __syncthreads();
    }
    if (j == 0) {
        float x = red[0] + pb2[0];
        out[N_MOLS + m] = 1.0f / (1.0f + expf(-x));
    }
}

// ---------------- launch ----------------
extern "C" void kernel_launch(void* const* d_in, const int* in_sizes, int n_in,
                              void* d_out, int out_size) {
    const int* z = (const int*)d_in[0];
    const float* pos = (const float*)d_in[1];
    const int* ei = (const int*)d_in[2];
    const int* batch = (const int*)d_in[3];
    const float* emb = (const float*)d_in[4];
    const float* fW1 = (const float*)d_in[5];
    const float* fb1 = (const float*)d_in[6];
    const float* fW2 = (const float*)d_in[7];
    const float* fb2 = (const float*)d_in[8];
    const float* uW1 = (const float*)d_in[9];
    const float* ub1 = (const float*)d_in[10];
    const float* uW2 = (const float*)d_in[11];
    const float* ub2 = (const float*)d_in[12];
    const float* lW1 = (const float*)d_in[13];
    const float* lb1 = (const float*)d_in[14];
    const float* lW2 = (const float*)d_in[15];
    const float* lb2 = (const float*)d_in[16];
    const float* pW1 = (const float*)d_in[17];
    const float* pb1 = (const float*)d_in[18];
    const float* pW2 = (const float*)d_in[19];
    const float* pb2 = (const float*)d_in[20];
    float* out = (float*)d_out;

    cudaFuncSetAttribute(table_kernel, cudaFuncAttributeMaxDynamicSharedMemorySize,
                         TAB_SMEM_FLOATS * 4);
    cudaFuncSetAttribute(node_kernel, cudaFuncAttributeMaxDynamicSharedMemorySize,
                         NODE_SMEM_FLOATS * 4);

    init_kernel<<<(NV + 255) / 256, 256>>>(z, emb);

    // CSR build
    const int scan_blocks = (N_ATOMS + SCAN_B - 1) / SCAN_B;
    hist_kernel<<<(N_EDGES + 255) / 256, 256>>>(ei);
    scan1_kernel<<<scan_blocks, SCAN_B>>>();
    scan2_kernel<<<1, 32>>>(scan_blocks);
    scan3_kernel<<<(N_ATOMS + 255) / 256, 256>>>();
    scatter_kernel<<<(N_EDGES + 255) / 256, 256>>>(ei, pos);

    table_kernel<<<dim3(TAB_D / 64, NLAYERS), 512, TAB_SMEM_FLOATS * 4>>>(fW1, fb1, fW2, fb2);

    const int msg_blocks = (N_ATOMS * 32 + 255) / 256;
    const int node_blocks = (N_ATOMS + NT - 1) / NT;
    for (int layer = 0; layer < NLAYERS; layer++) {
        msg_kernel<<<msg_blocks, 256>>>(layer);
        node_kernel<<<node_blocks, 256, NODE_SMEM_FLOATS * 4>>>(layer, uW1, ub1, uW2, ub2);
    }

    pool_zero_kernel<<<(N_MOLS * HID + 255) / 256, 256>>>();
    pool_acc_kernel<<<(NV + 255) / 256, 256>>>(batch);
    head_kernel<<<N_MOLS, HID>>>(lW1, lb1, lW2, lb2, pW1, pb1, pW2, pb2, out);
}

// round 5
// speedup vs baseline: 4.1043x; 1.0114x over previous
#include <cuda_runtime.h>
#include <cuda_fp16.h>
#include <math.h>

#define N_ATOMS 50000
#define N_EDGES 400000
#define N_MOLS  500
#define HID     128
#define NRBF    20
#define NLAYERS 4
#define NV      (N_ATOMS * HID)

#define TAB_D   8192
#define TAB_MAX 12.0f
#define RBF_STEP (5.0f / (float)(NRBF - 1))

typedef unsigned long long ull;

// ---------------- device scratch ----------------
__device__ float g_s[NV];
__device__ float g_v[3 * NV];    // planar [3][N][HID]
__device__ float g_ms[NV];
__device__ float g_mv[3 * NV];   // planar [3][N][HID]
__device__ __half2 g_htabh[NLAYERS * TAB_D * 3 * HID];  // (.x = h(i), .y = h(i+1))
__device__ float g_hmol[N_MOLS * HID];
__device__ float g_cnt[N_MOLS];

// CSR scratch
__device__ int   g_deg[N_ATOMS];
__device__ int   g_rowptr[N_ATOMS + 1];
__device__ int   g_cursor[N_ATOMS];
__device__ int   g_bsum[128];
__device__ int   g_ecol[N_EDGES];
__device__ float4 g_egeo[N_EDGES];   // (dirx, diry, dirz, dist)

__device__ __forceinline__ float silu_f(float x) { return x / (1.0f + expf(-x)); }

__device__ __forceinline__ ull pack2(float lo, float hi) {
    ull r;
    asm("mov.b64 %0, {%1, %2};" : "=l"(r) : "f"(lo), "f"(hi));
    return r;
}
__device__ __forceinline__ void unpack2(ull v, float& lo, float& hi) {
    asm("mov.b64 {%0, %1}, %2;" : "=f"(lo), "=f"(hi) : "l"(v));
}
#define FMA_F32X2(acc, a, b) \
    asm("fma.rn.f32x2 %0, %1, %2, %0;" : "+l"(acc) : "l"(a), "l"(b))

// ---------------- init ----------------
__global__ void init_kernel(const int* __restrict__ z, const float* __restrict__ emb) {
    int idx = blockIdx.x * blockDim.x + threadIdx.x;
    if (idx < N_ATOMS) g_deg[idx] = 0;
    if (idx >= NV) return;
    int n = idx >> 7;
    int j = idx & 127;
    g_s[idx] = emb[z[n] * HID + j];
    g_v[idx] = 0.0f; g_v[NV + idx] = 0.0f; g_v[2 * NV + idx] = 0.0f;
}

// ---------------- CSR build ----------------
__global__ void hist_kernel(const int* __restrict__ ei) {
    int e = blockIdx.x * blockDim.x + threadIdx.x;
    if (e >= N_EDGES) return;
    atomicAdd(&g_deg[ei[e]], 1);
}

#define SCAN_B 512
__global__ void scan1_kernel() {
    __shared__ int s[SCAN_B];
    int t = threadIdx.x;
    int i = blockIdx.x * SCAN_B + t;
    int v = (i < N_ATOMS) ? g_deg[i] : 0;
    s[t] = v;
    __syncthreads();
    for (int off = 1; off < SCAN_B; off <<= 1) {
        int add = (t >= off) ? s[t - off] : 0;
        __syncthreads();
        s[t] += add;
        __syncthreads();
    }
    if (i < N_ATOMS) g_rowptr[i] = s[t] - v;
    if (t == SCAN_B - 1) g_bsum[blockIdx.x] = s[t];
}

__global__ void scan2_kernel(int nblocks) {
    if (threadIdx.x == 0) {
        int run = 0;
        for (int b = 0; b < nblocks; b++) {
            int t = g_bsum[b];
            g_bsum[b] = run;
            run += t;
        }
    }
}

__global__ void scan3_kernel() {
    int i = blockIdx.x * blockDim.x + threadIdx.x;
    if (i < N_ATOMS) {
        int rp = g_rowptr[i] + g_bsum[i >> 9];
        g_rowptr[i] = rp;
        g_cursor[i] = rp;
    }
    if (i == 0) g_rowptr[N_ATOMS] = N_EDGES;
}

__global__ void scatter_kernel(const int* __restrict__ ei, const float* __restrict__ pos) {
    int e = blockIdx.x * blockDim.x + threadIdx.x;
    if (e >= N_EDGES) return;
    int r = ei[e];
    int c = ei[N_EDGES + e];
    float dx = pos[c * 3 + 0] - pos[r * 3 + 0];
    float dy = pos[c * 3 + 1] - pos[r * 3 + 1];
    float dz = pos[c * 3 + 2] - pos[r * 3 + 2];
    float dist = sqrtf(dx * dx + dy * dy + dz * dz);
    float inv = 1.0f / (dist + 1e-8f);
    int p = atomicAdd(&g_cursor[r], 1);
    g_ecol[p] = c;
    g_egeo[p] = make_float4(dx * inv, dy * inv, dz * inv, dist);
}

// ---------------- filter table build (fp32 math, half2 endpoint store) ----------------
#define TAB_SMEM_FLOATS 20736

extern "C" __global__ void __launch_bounds__(512, 1)
table_kernel(const float* __restrict__ fW1, const float* __restrict__ fb1,
             const float* __restrict__ fW2, const float* __restrict__ fb2) {
    extern __shared__ float sm[];
    float* hid = sm;                 // [64][132]
    float* rbf_s = sm + 8448;        // [64][20]
    float* w1_s = sm + 9728;         // [20][128]
    float* w2_s = sm + 8448;         // [32][384] (stage2, overlaps)

    const int tid = threadIdx.x;
    const int layer = blockIdx.y;
    const int g0 = blockIdx.x * 64;
    const float* W1 = fW1 + layer * NRBF * HID;
    const float* b1 = fb1 + layer * HID;
    const float* W2 = fW2 + layer * HID * 3 * HID;
    const float* b2 = fb2 + layer * 3 * HID;
    const float DELTA = TAB_MAX / (float)(TAB_D - 1);

    for (int idx = tid; idx < 64 * NRBF; idx += 512) {
        int e = idx / NRBF, k = idx % NRBF;
        float d = (float)(g0 + e) * DELTA - RBF_STEP * (float)k;
        rbf_s[idx] = expf(-d * d);
    }
    for (int idx = tid; idx < NRBF * HID; idx += 512) w1_s[idx] = W1[idx];
    __syncthreads();

    const int jg = tid & 31;
    const int eg = tid >> 5;
    const int j0 = jg * 4;
    const int el0 = eg * 4;

    float hacc[4][4];
#pragma unroll
    for (int a = 0; a < 4; a++)
#pragma unroll
        for (int b = 0; b < 4; b++) hacc[a][b] = b1[j0 + b];
#pragma unroll
    for (int k = 0; k < NRBF; k++) {
        float r[4];
#pragma unroll
        for (int a = 0; a < 4; a++) r[a] = rbf_s[(el0 + a) * NRBF + k];
        float4 w = *(const float4*)&w1_s[k * HID + j0];
        float wv[4] = {w.x, w.y, w.z, w.w};
#pragma unroll
        for (int a = 0; a < 4; a++)
#pragma unroll
            for (int b = 0; b < 4; b++) hacc[a][b] += r[a] * wv[b];
    }
#pragma unroll
    for (int a = 0; a < 4; a++)
#pragma unroll
        for (int b = 0; b < 4; b++) hid[(el0 + a) * 132 + j0 + b] = silu_f(hacc[a][b]);
    __syncthreads();

    float a_ss[4][4], a_vv[4][4], a_sv[4][4];
#pragma unroll
    for (int a = 0; a < 4; a++)
#pragma unroll
        for (int b = 0; b < 4; b++) { a_ss[a][b] = 0.f; a_vv[a][b] = 0.f; a_sv[a][b] = 0.f; }

    for (int kc = 0; kc < HID; kc += 32) {
        __syncthreads();
        for (int idx = tid; idx < 32 * 384; idx += 512) w2_s[idx] = W2[kc * 384 + idx];
        __syncthreads();
#pragma unroll 8
        for (int kk = 0; kk < 32; kk++) {
            float h[4];
#pragma unroll
            for (int a = 0; a < 4; a++) h[a] = hid[(el0 + a) * 132 + kc + kk];
            float4 wss = *(const float4*)&w2_s[kk * 384 + j0];
            float4 wvv = *(const float4*)&w2_s[kk * 384 + 128 + j0];
            float4 wsv = *(const float4*)&w2_s[kk * 384 + 256 + j0];
            float ss[4] = {wss.x, wss.y, wss.z, wss.w};
            float vv[4] = {wvv.x, wvv.y, wvv.z, wvv.w};
            float sv[4] = {wsv.x, wsv.y, wsv.z, wsv.w};
#pragma unroll
            for (int a = 0; a < 4; a++)
#pragma unroll
                for (int b = 0; b < 4; b++) {
                    a_ss[a][b] += h[a] * ss[b];
                    a_vv[a][b] += h[a] * vv[b];
                    a_sv[a][b] += h[a] * sv[b];
                }
        }
    }

    // write h(gi) as .x of entry gi and .y of entry gi-1 (lerp endpoints co-located)
#pragma unroll
    for (int a = 0; a < 4; a++) {
        int gi = g0 + el0 + a;
        __half* Tx = (__half*)(g_htabh + ((size_t)layer * TAB_D + gi) * 384);
        __half* Ty = (__half*)(g_htabh + ((size_t)layer * TAB_D + gi - 1) * 384);
#pragma unroll
        for (int b = 0; b < 4; b++) {
            float hss = a_ss[a][b] + b2[j0 + b];
            float hvv = a_vv[a][b] + b2[128 + j0 + b];
            float hsv = a_sv[a][b] + b2[256 + j0 + b];
            Tx[(j0 + b) * 2]         = __float2half(hss);
            Tx[(128 + j0 + b) * 2]   = __float2half(hvv);
            Tx[(256 + j0 + b) * 2]   = __float2half(hsv);
            if (gi > 0) {
                Ty[(j0 + b) * 2 + 1]       = __float2half(hss);
                Ty[(128 + j0 + b) * 2 + 1] = __float2half(hvv);
                Ty[(256 + j0 + b) * 2 + 1] = __float2half(hsv);
            }
        }
    }
}

// ---------------- edge message kernel: CSR segment-sum, warp per row ----------------
extern "C" __global__ void __launch_bounds__(256)
msg_kernel(int layer) {
    int r = (blockIdx.x * 256 + threadIdx.x) >> 5;
    int lane = threadIdx.x & 31;
    if (r >= N_ATOMS) return;

    int beg = g_rowptr[r];
    int end = g_rowptr[r + 1];

    const float INV_DELTA = (float)(TAB_D - 1) / TAB_MAX;
    const __half2* Tl = g_htabh + (size_t)layer * TAB_D * 384;

    float accS[4] = {0.f, 0.f, 0.f, 0.f};
    float accV[12];
#pragma unroll
    for (int q = 0; q < 12; q++) accV[q] = 0.f;

    for (int p = beg; p < end; p++) {
        int col = g_ecol[p];
        float4 geo = g_egeo[p];
        float u = geo.w * INV_DELTA;
        int i0 = (int)u;
        if (i0 > TAB_D - 2) i0 = TAB_D - 2;
        float f = u - (float)i0;
        const __half2* T = Tl + (size_t)i0 * 384;

#pragma unroll
        for (int b = 0; b < 4; b++) {
            int j = lane + 32 * b;
            float2 pss = __half22float2(__ldcg(&T[j]));
            float2 pvv = __half22float2(__ldcg(&T[128 + j]));
            float2 psv = __half22float2(__ldcg(&T[256 + j]));
            float hss = pss.x + f * (pss.y - pss.x);
            float hvv = pvv.x + f * (pvv.y - pvv.x);
            float hsv = psv.x + f * (psv.y - psv.x);
            float sc = __ldcg(&g_s[col * HID + j]);
            accS[b] += hss * sc;
            float cc = hsv * sc;
            accV[b]     += hvv * __ldcg(&g_v[col * HID + j])          + cc * geo.x;
            accV[4 + b] += hvv * __ldcg(&g_v[NV + col * HID + j])     + cc * geo.y;
            accV[8 + b] += hvv * __ldcg(&g_v[2 * NV + col * HID + j]) + cc * geo.z;
        }
    }

#pragma unroll
    for (int b = 0; b < 4; b++) {
        int j = lane + 32 * b;
        g_ms[r * HID + j] = accS[b];
        g_mv[r * HID + j] = accV[b];
        g_mv[NV + r * HID + j] = accV[4 + b];
        g_mv[2 * NV + r * HID + j] = accV[8 + b];
    }
}

// ---------------- node update kernel (packed f32x2 FMA) ----------------
// 64 nodes/block, 256 threads, 8x4 micro-tile paired along nodes, 2 CTAs/SM.
#define NT 64
#define XS_STRIDE 76
#define NODE_SMEM_FLOATS 22784

extern "C" __global__ void __launch_bounds__(256, 2)
node_kernel(int layer,
            const float* __restrict__ uW1, const float* __restrict__ ub1,
            const float* __restrict__ uW2, const float* __restrict__ ub2) {
    extern __shared__ float sm[];
    float* xs_t = sm;              // [64 k][76]
    float* wc   = sm + 4864;       // [64 k][128]
    float* ts_t = sm + 13056;      // [128 k][76]

    const int tid = threadIdx.x;
    const int n0 = blockIdx.x * NT;
    const float* W1 = uW1 + layer * 384 * HID;
    const float* b1 = ub1 + layer * HID;
    const float* W2 = uW2 + layer * HID * 384;
    const float* b2 = ub2 + layer * 384;

    const int og = tid & 31;
    const int ng = tid >> 5;
    const int j0 = og * 4;
    const int nl0 = ng * 8;

    float4 wreg[8];
#pragma unroll
    for (int q = 0; q < 8; q++) {
        int idx = q * 256 + tid;
        int k = idx >> 5, c4 = idx & 31;
        wreg[q] = *(const float4*)&W1[k * HID + c4 * 4];
    }

    // ---- stage 1: t = silu(x @ W1 + b1) ----
    float4 b1v = *(const float4*)&b1[j0];
    ull accP[4][4];
    {
        float bb[4] = {b1v.x, b1v.y, b1v.z, b1v.w};
#pragma unroll
        for (int ap = 0; ap < 4; ap++)
#pragma unroll
            for (int b = 0; b < 4; b++) accP[ap][b] = pack2(bb[b], bb[b]);
    }

    for (int kc = 0; kc < 384; kc += 64) {
        __syncthreads();
#pragma unroll
        for (int q = 0; q < 8; q++) {
            int idx = q * 256 + tid;
            int k = idx >> 5, c4 = idx & 31;
            *(float4*)&wc[k * 128 + c4 * 4] = wreg[q];
        }
        for (int idx = tid; idx < 64 * 64; idx += 256) {
            int node = idx >> 6, k = idx & 63;
            int gk = kc + k, gn = n0 + node;
            float val = 0.f;
            if (gn < N_ATOMS) {
                if (gk < 128) {
                    val = g_s[gn * HID + gk];
                } else if (gk < 256) {
                    val = g_ms[gn * HID + (gk - 128)];
                } else {
                    int p = gn * HID + (gk - 256);
                    float mx = g_mv[p], my = g_mv[NV + p], mz = g_mv[2 * NV + p];
                    val = sqrtf(mx * mx + my * my + mz * mz);
                }
            }
            xs_t[k * XS_STRIDE + node] = val;
        }
        __syncthreads();
        if (kc + 64 < 384) {
#pragma unroll
            for (int q = 0; q < 8; q++) {
                int idx = q * 256 + tid;
                int k = idx >> 5, c4 = idx & 31;
                wreg[q] = *(const float4*)&W1[(kc + 64 + k) * HID + c4 * 4];
            }
        } else {
#pragma unroll
            for (int q = 0; q < 8; q++) {
                int idx = q * 256 + tid;
                int k = idx >> 5, c4 = idx & 31;
                wreg[q] = *(const float4*)&W2[k * 384 + c4 * 4];
            }
        }
#pragma unroll 4
        for (int kk = 0; kk < 64; kk++) {
            const ull* ax = (const ull*)&xs_t[kk * XS_STRIDE + nl0];
            ull a0 = ax[0], a1 = ax[1], a2 = ax[2], a3 = ax[3];
            float4 w = *(const float4*)&wc[kk * 128 + j0];
            ull w0 = pack2(w.x, w.x), w1 = pack2(w.y, w.y);
            ull w2 = pack2(w.z, w.z), w3 = pack2(w.w, w.w);
            FMA_F32X2(accP[0][0], a0, w0); FMA_F32X2(accP[1][0], a1, w0);
            FMA_F32X2(accP[2][0], a2, w0); FMA_F32X2(accP[3][0], a3, w0);
            FMA_F32X2(accP[0][1], a0, w1); FMA_F32X2(accP[1][1], a1, w1);
            FMA_F32X2(accP[2][1], a2, w1); FMA_F32X2(accP[3][1], a3, w1);
            FMA_F32X2(accP[0][2], a0, w2); FMA_F32X2(accP[1][2], a1, w2);
            FMA_F32X2(accP[2][2], a2, w2); FMA_F32X2(accP[3][2], a3, w2);
            FMA_F32X2(accP[0][3], a0, w3); FMA_F32X2(accP[1][3], a1, w3);
            FMA_F32X2(accP[2][3], a2, w3); FMA_F32X2(accP[3][3], a3, w3);
        }
    }
#pragma unroll
    for (int ap = 0; ap < 4; ap++)
#pragma unroll
        for (int b = 0; b < 4; b++) {
            float lo, hi;
            unpack2(accP[ap][b], lo, hi);
            ts_t[(j0 + b) * XS_STRIDE + nl0 + 2 * ap] = silu_f(lo);
            ts_t[(j0 + b) * XS_STRIDE + nl0 + 2 * ap + 1] = silu_f(hi);
        }

    // ---- stage 2: u = t @ W2 + b2 ----
    ull u2P[4][4];
    for (int c = 0; c < 6; c++) {
        int jb = c >> 1;
        int kc2 = (c & 1) * 64;
        if (kc2 == 0) {
#pragma unroll
            for (int ap = 0; ap < 4; ap++)
#pragma unroll
                for (int b = 0; b < 4; b++) u2P[ap][b] = 0ull;
        }
        __syncthreads();
#pragma unroll
        for (int q = 0; q < 8; q++) {
            int idx = q * 256 + tid;
            int k = idx >> 5, c4 = idx & 31;
            *(float4*)&wc[k * 128 + c4 * 4] = wreg[q];
        }
        __syncthreads();
        if (c < 5) {
            int cn = c + 1;
            int jbn = cn >> 1;
            int kc2n = (cn & 1) * 64;
#pragma unroll
            for (int q = 0; q < 8; q++) {
                int idx = q * 256 + tid;
                int k = idx >> 5, c4 = idx & 31;
                wreg[q] = *(const float4*)&W2[(kc2n + k) * 384 + jbn * 128 + c4 * 4];
            }
        }
#pragma unroll 4
        for (int kk = 0; kk < 64; kk++) {
            const ull* ax = (const ull*)&ts_t[(kc2 + kk) * XS_STRIDE + nl0];
            ull a0 = ax[0], a1 = ax[1], a2 = ax[2], a3 = ax[3];
            float4 w = *(const float4*)&wc[kk * 128 + j0];
            ull w0 = pack2(w.x, w.x), w1 = pack2(w.y, w.y);
            ull w2 = pack2(w.z, w.z), w3 = pack2(w.w, w.w);
            FMA_F32X2(u2P[0][0], a0, w0); FMA_F32X2(u2P[1][0], a1, w0);
            FMA_F32X2(u2P[2][0], a2, w0); FMA_F32X2(u2P[3][0], a3, w0);
            FMA_F32X2(u2P[0][1], a0, w1); FMA_F32X2(u2P[1][1], a1, w1);
            FMA_F32X2(u2P[2][1], a2, w1); FMA_F32X2(u2P[3][1], a3, w1);
            FMA_F32X2(u2P[0][2], a0, w2); FMA_F32X2(u2P[1][2], a1, w2);
            FMA_F32X2(u2P[2][2], a2, w2); FMA_F32X2(u2P[3][2], a3, w2);
            FMA_F32X2(u2P[0][3], a0, w3); FMA_F32X2(u2P[1][3], a1, w3);
            FMA_F32X2(u2P[2][3], a2, w3); FMA_F32X2(u2P[3][3], a3, w3);
        }

        if (kc2 == 64) {
            float u2[8][4];
#pragma unroll
            for (int ap = 0; ap < 4; ap++)
#pragma unroll
                for (int b = 0; b < 4; b++)
                    unpack2(u2P[ap][b], u2[2 * ap][b], u2[2 * ap + 1][b]);

            float4 b2v = *(const float4*)&b2[jb * 128 + j0];
            float bb[4] = {b2v.x, b2v.y, b2v.z, b2v.w};
#pragma unroll
            for (int a = 0; a < 8; a++) {
                int gn = n0 + nl0 + a;
                if (gn >= N_ATOMS) continue;
                if (jb == 0) {
#pragma unroll
                    for (int b = 0; b < 4; b++)
                        g_s[gn * HID + j0 + b] += u2[a][b] + bb[b];
                } else if (jb == 1) {
#pragma unroll
                    for (int d = 0; d < 3; d++) {
                        float4* vp = (float4*)&g_v[d * NV + gn * HID + j0];
                        float4 vv = *vp;
                        vv.x *= (u2[a][0] + bb[0]);
                        vv.y *= (u2[a][1] + bb[1]);
                        vv.z *= (u2[a][2] + bb[2]);
                        vv.w *= (u2[a][3] + bb[3]);
                        *vp = vv;
                    }
                } else {
#pragma unroll
                    for (int d = 0; d < 3; d++) {
                        float4* vp = (float4*)&g_v[d * NV + gn * HID + j0];
                        const float4* mp = (const float4*)&g_mv[d * NV + gn * HID + j0];
                        float4 vv = *vp;
                        float4 mv = *mp;
                        vv.x += (u2[a][0] + bb[0]) * mv.x;
                        vv.y += (u2[a][1] + bb[1]) * mv.y;
                        vv.z += (u2[a][2] + bb[2]) * mv.z;
                        vv.w += (u2[a][3] + bb[3]) * mv.w;
                        *vp = vv;
                    }
                }
            }
        }
    }
}

// ---------------- molecule pooling + heads ----------------
__global__ void pool_zero_kernel() {
    int idx = blockIdx.x * blockDim.x + threadIdx.x;
    if (idx < N_MOLS * HID) g_hmol[idx] = 0.f;
    if (idx < N_MOLS) g_cnt[idx] = 0.f;
}

__global__ void pool_acc_kernel(const int* __restrict__ batch) {
    int idx = blockIdx.x * blockDim.x + threadIdx.x;
    if (idx >= NV) return;
    int n = idx >> 7;
    int j = idx & 127;
    int m = batch[n];
    atomicAdd(&g_hmol[m * HID + j], g_s[idx]);
    if (j == 0) atomicAdd(&g_cnt[m], 1.0f);
}

__global__ void head_kernel(const float* __restrict__ lW1, const float* __restrict__ lb1,
                            const float* __restrict__ lW2, const float* __restrict__ lb2,
                            const float* __restrict__ pW1, const float* __restrict__ pb1,
                            const float* __restrict__ pW2, const float* __restrict__ pb2,
                            float* __restrict__ out) {
    __shared__ float hm[HID];
    __shared__ float tt[HID];
    __shared__ float red[HID];
    int m = blockIdx.x;
    int j = threadIdx.x;
    float cnt = g_cnt[m];
    hm[j] = g_hmol[m * HID + j] / cnt;
    __syncthreads();

    float acc = lb1[j];
    for (int k = 0; k < HID; k++) acc += hm[k] * lW1[k * HID + j];
    tt[j] = silu_f(acc);
    __syncthreads();
    red[j] = tt[j] * lW2[j];
    __syncthreads();
    for (int s = 64; s > 0; s >>= 1) {
        if (j < s) red[j] += red[j + s];
        __syncthreads();
    }
    if (j == 0) out[m] = red[0] + lb2[0];
    __syncthreads();

    acc = pb1[j];
    for (int k = 0; k < HID; k++) acc += hm[k] * pW1[k * HID + j];
    tt[j] = silu_f(acc);
    __syncthreads();
    red[j] = tt[j] * pW2[j];
    __syncthreads();
    for (int s = 64; s > 0; s >>= 1) {
        if (j < s) red[j] += red[j + s];
        __syncthreads();
    }
    if (j == 0) {
        float x = red[0] + pb2[0];
        out[N_MOLS + m] = 1.0f / (1.0f + expf(-x));
    }
}

// ---------------- launch ----------------
extern "C" void kernel_launch(void* const* d_in, const int* in_sizes, int n_in,
                              void* d_out, int out_size) {
    const int* z = (const int*)d_in[0];
    const float* pos = (const float*)d_in[1];
    const int* ei = (const int*)d_in[2];
    const int* batch = (const int*)d_in[3];
    const float* emb = (const float*)d_in[4];
    const float* fW1 = (const float*)d_in[5];
    const float* fb1 = (const float*)d_in[6];
    const float* fW2 = (const float*)d_in[7];
    const float* fb2 = (const float*)d_in[8];
    const float* uW1 = (const float*)d_in[9];
    const float* ub1 = (const float*)d_in[10];
    const float* uW2 = (const float*)d_in[11];
    const float* ub2 = (const float*)d_in[12];
    const float* lW1 = (const float*)d_in[13];
    const float* lb1 = (const float*)d_in[14];
    const float* lW2 = (const float*)d_in[15];
    const float* lb2 = (const float*)d_in[16];
    const float* pW1 = (const float*)d_in[17];
    const float* pb1 = (const float*)d_in[18];
    const float* pW2 = (const float*)d_in[19];
    const float* pb2 = (const float*)d_in[20];
    float* out = (float*)d_out;

    cudaFuncSetAttribute(table_kernel, cudaFuncAttributeMaxDynamicSharedMemorySize,
                         TAB_SMEM_FLOATS * 4);
    cudaFuncSetAttribute(node_kernel, cudaFuncAttributeMaxDynamicSharedMemorySize,
                         NODE_SMEM_FLOATS * 4);

    init_kernel<<<(NV + 255) / 256, 256>>>(z, emb);

    const int scan_blocks = (N_ATOMS + SCAN_B - 1) / SCAN_B;
    hist_kernel<<<(N_EDGES + 255) / 256, 256>>>(ei);
    scan1_kernel<<<scan_blocks, SCAN_B>>>();
    scan2_kernel<<<1, 32>>>(scan_blocks);
    scan3_kernel<<<(N_ATOMS + 255) / 256, 256>>>();
    scatter_kernel<<<(N_EDGES + 255) / 256, 256>>>(ei, pos);

    table_kernel<<<dim3(TAB_D / 64, NLAYERS), 512, TAB_SMEM_FLOATS * 4>>>(fW1, fb1, fW2, fb2);

    const int msg_blocks = (N_ATOMS * 32 + 255) / 256;
    const int node_blocks = (N_ATOMS + NT - 1) / NT;
    for (int layer = 0; layer < NLAYERS; layer++) {
        msg_kernel<<<msg_blocks, 256>>>(layer);
        node_kernel<<<node_blocks, 256, NODE_SMEM_FLOATS * 4>>>(layer, uW1, ub1, uW2, ub2);
    }

    pool_zero_kernel<<<(N_MOLS * HID + 255) / 256, 256>>>();
    pool_acc_kernel<<<(NV + 255) / 256, 256>>>(batch);
    head_kernel<<<N_MOLS, HID>>>(lW1, lb1, lW2, lb2, pW1, pb1, pW2, pb2, out);
}